// round 13
// baseline (speedup 1.0000x reference)
#include <cuda_runtime.h>
#include <cstdint>

#define BATCH 4
#define NPTS 4096
#define KOUT 16
#define NEED 31                 // rank 0 plus ranks 16..30
#define R2 256.0f
#define TPB 512
#define WARPS (TPB / 32)        // 16
#define NBLOCKS 296             // 148 SMs * 2 resident blocks
#define WPB_PER_BATCH ((NBLOCKS / BATCH) * WARPS)        // 1184
#define PERIOD (NPTS + WPB_PER_BATCH)                    // 5280
#define NK ((size_t)NPTS * KOUT)                         // 65536

#define NC 12
#define NCELLS (NC * NC * NC)   // 1728
#define CELL 24.0f
#define GOFF 144.0f
#define INV_CELL (1.0f / 24.0f)
#define PRUNE_R2 289.0f         // 17^2: covers fp fuzz at the d2<256 boundary

// steal counters: never reset; q = ctr % PERIOD is deterministic per replay
__device__ unsigned g_ctr[BATCH];
// grid CSR + packed points (scratch; rebuilt every launch)
__device__ float4 g_pts[BATCH * NPTS];
__device__ int g_starts[BATCH][NCELLS + 1];
__device__ int g_perm[BATCH * NPTS];

// exact arithmetic (matches reference decisions; rel_err 0.0 with this)
static __device__ __forceinline__ float dist2(float4 a, float4 b) {
    float dot = __fadd_rn(
        __fadd_rn(__fmul_rn(a.x, b.x), __fmul_rn(a.y, b.y)),
        __fmul_rn(a.z, b.z));
    return __fsub_rn(__fadd_rn(a.w, b.w), __fmul_rn(2.0f, dot));
}

static __device__ __forceinline__ int cellco(float v) {
    int c = (int)floorf((v + GOFF) * INV_CELL);
    return c < 0 ? 0 : (c > NC - 1 ? NC - 1 : c);
}

// ---------------------------------------------------------------------------
// Build kernel: one block per batch. Packs points (x,y,z,|p|^2) and builds a
// counting-sort CSR (hist -> block scan -> scatter). Scatter order within a
// cell is atomic-arbitrary; downstream output is order-independent (bitmap).
// ---------------------------------------------------------------------------
__global__ void __launch_bounds__(512) build_kernel(const float* __restrict__ xyz) {
    __shared__ int hist[2048];
    __shared__ int wsums[16];
    int b = blockIdx.x;
    const float* xb = xyz + (size_t)b * NPTS * 3;
    int t = threadIdx.x;
    int lane = t & 31, wid = t >> 5;

    for (int i = t; i < 2048; i += 512) hist[i] = 0;
    __syncthreads();

    int mycell[NPTS / 512];
#pragma unroll
    for (int j = 0; j < NPTS / 512; j++) {
        int i = t + j * 512;
        float x = xb[3 * i], y = xb[3 * i + 1], z = xb[3 * i + 2];
        float w = __fadd_rn(__fadd_rn(__fmul_rn(x, x), __fmul_rn(y, y)),
                            __fmul_rn(z, z));
        g_pts[b * NPTS + i] = make_float4(x, y, z, w);
        int cell = (cellco(x) * NC + cellco(y)) * NC + cellco(z);
        mycell[j] = cell;
        atomicAdd(&hist[cell], 1);
    }
    __syncthreads();

    // block exclusive scan over 2048 counts (4 per thread)
    int h0 = hist[4 * t + 0], h1 = hist[4 * t + 1];
    int h2 = hist[4 * t + 2], h3 = hist[4 * t + 3];
    int v = h0 + h1 + h2 + h3;
    int pre = v;
#pragma unroll
    for (int o = 1; o < 32; o <<= 1) {
        int u = __shfl_up_sync(0xffffffffu, pre, o);
        if (lane >= o) pre += u;
    }
    if (lane == 31) wsums[wid] = pre;
    __syncthreads();
    if (t == 0) {
        int acc = 0;
        for (int i = 0; i < 16; i++) { int tmp = wsums[i]; wsums[i] = acc; acc += tmp; }
    }
    __syncthreads();
    int e = pre - v + wsums[wid];       // exclusive offset of cell 4t
    __syncthreads();                    // all reads of hist done

    hist[4 * t + 0] = e;
    hist[4 * t + 1] = e + h0;
    hist[4 * t + 2] = e + h0 + h1;
    hist[4 * t + 3] = e + h0 + h1 + h2;
    if (4 * t < NCELLS) {
        g_starts[b][4 * t + 0] = e;
        g_starts[b][4 * t + 1] = e + h0;
        g_starts[b][4 * t + 2] = e + h0 + h1;
        g_starts[b][4 * t + 3] = e + h0 + h1 + h2;
    }
    if (t == 0) g_starts[b][NCELLS] = NPTS;
    __syncthreads();

#pragma unroll
    for (int j = 0; j < NPTS / 512; j++) {
        int i = t + j * 512;
        int pos = atomicAdd(&hist[mycell[j]], 1);
        g_perm[b * NPTS + pos] = i;
    }
}

// ---------------------------------------------------------------------------
// Fused kernel: grid-pruned ball query -> hit bitmap -> rank decode ->
// transposing gather epilogue. Warp per query (work-stealing).
// ---------------------------------------------------------------------------
__global__ void __launch_bounds__(TPB, 2) fused_kernel(
        const float* __restrict__ feat,
        float* __restrict__ out) {
    extern __shared__ float4 s[];                       // 4096 float4 = 64KB
    __shared__ unsigned words[WARPS][128];              // hit bitmaps
    __shared__ int oid[WARPS][KOUT + 1];
    __shared__ float4 stage[WARPS][128];                // 16 rows x 8 f4 = 2KB

    int b = blockIdx.x % BATCH;

    for (int i = threadIdx.x; i < NPTS; i += blockDim.x)
        s[i] = g_pts[b * NPTS + i];
    __syncthreads();

    int warp = threadIdx.x >> 5;
    int lane = threadIdx.x & 31;
    const float* fb = feat + (size_t)b * NPTS * 64;
    const int* permb = g_perm + b * NPTS;
    float* outx = out + ((size_t)b * 3) * NK;                 // xyz block
    float* outf = out + (size_t)BATCH * 3 * NK + ((size_t)b * 64) * NK;

    for (;;) {
        unsigned qr = 0;
        if (lane == 0) qr = atomicAdd(&g_ctr[b], 1u) % PERIOD;
        int q = __shfl_sync(0xffffffffu, (int)qr, 0);
        if (q >= NPTS) break;

        // zero bitmap
#pragma unroll
        for (int i = 0; i < 4; i++) words[warp][lane + 32 * i] = 0u;
        __syncwarp();

        float4 pq = s[q];
        int cnt = 0;

        // cell ranges (uniform across warp: pq identical in all lanes)
        int c0x = cellco(pq.x - 17.0f), c1x = cellco(pq.x + 17.0f);
        int c0y = cellco(pq.y - 17.0f), c1y = cellco(pq.y + 17.0f);
        int c0z = cellco(pq.z - 17.0f), c1z = cellco(pq.z + 17.0f);

        // per-dim box penetration^2 tables (boundary cells unbounded)
        float dx2[3], dy2[3], dz2[3];
#pragma unroll
        for (int i = 0; i < 3; i++) {
            { int c = c0x + i;
              if (c > c1x) dx2[i] = 1e30f;
              else {
                  float lo = (c == 0) ? -1e30f : c * CELL - GOFF;
                  float hi = (c == NC - 1) ? 1e30f : c * CELL - GOFF + CELL;
                  float d = fmaxf(fmaxf(lo - pq.x, pq.x - hi), 0.0f);
                  dx2[i] = d * d; } }
            { int c = c0y + i;
              if (c > c1y) dy2[i] = 1e30f;
              else {
                  float lo = (c == 0) ? -1e30f : c * CELL - GOFF;
                  float hi = (c == NC - 1) ? 1e30f : c * CELL - GOFF + CELL;
                  float d = fmaxf(fmaxf(lo - pq.y, pq.y - hi), 0.0f);
                  dy2[i] = d * d; } }
            { int c = c0z + i;
              if (c > c1z) dz2[i] = 1e30f;
              else {
                  float lo = (c == 0) ? -1e30f : c * CELL - GOFF;
                  float hi = (c == NC - 1) ? 1e30f : c * CELL - GOFF + CELL;
                  float d = fmaxf(fmaxf(lo - pq.z, pq.z - hi), 0.0f);
                  dz2[i] = d * d; } }
        }

        // pruned candidate scan
#pragma unroll
        for (int ix = 0; ix < 3; ix++) {
            if (dx2[ix] >= PRUNE_R2) continue;
#pragma unroll
            for (int iy = 0; iy < 3; iy++) {
                float dxy = dx2[ix] + dy2[iy];
                if (dxy >= PRUNE_R2) continue;
                int cb = ((c0x + ix) * NC + (c0y + iy)) * NC;
#pragma unroll
                for (int iz = 0; iz < 3; iz++) {
                    if (dxy + dz2[iz] >= PRUNE_R2) continue;
                    int cell = cb + c0z + iz;
                    int st = g_starts[b][cell];
                    int en = g_starts[b][cell + 1];
                    for (int j0 = st; j0 < en; j0 += 32) {
                        int j = j0 + lane;
                        bool valid = j < en;
                        int idx = valid ? permb[j] : 0;
                        float4 p = s[idx];
                        bool hit = valid && (dist2(pq, p) < R2);
                        unsigned m = __ballot_sync(0xffffffffu, hit);
                        if (hit)
                            atomicOr(&words[warp][idx >> 5],
                                     1u << (idx & 31));
                        cnt += __popc(m);
                    }
                }
            }
        }
        __syncwarp();

        // ---- decode: rank 0 and ranks 16..30 from the hit bitmap ----
        int base = 0;
#pragma unroll
        for (int g = 0; g < 4; g++) {
            if (base >= NEED) break;
            int wi = 32 * g + lane;
            unsigned w = words[warp][wi];
            int pc = __popc(w);
            int pre = pc;                          // inclusive warp scan
#pragma unroll
            for (int o = 1; o < 32; o <<= 1) {
                int t = __shfl_up_sync(0xffffffffu, pre, o);
                if (lane >= o) pre += t;
            }
            int lo = base + pre - pc;              // first rank in my word
            if (w && lo < NEED) {
                unsigned ww = w;
                int r = lo;
                while (ww && r < NEED) {
                    int bit = __ffs(ww) - 1;
                    ww &= ww - 1;
                    if (r == 0)
                        oid[warp][0] = 32 * wi + bit;
                    else if (r >= 16)
                        oid[warp][r - 15] = 32 * wi + bit;
                    r++;
                }
            }
            base += __shfl_sync(0xffffffffu, pre, 31);
        }
        __syncwarp();

        // finalize ids (padding with first hit) back into oid[warp][k]
        if (lane < KOUT) {
            int v = (lane > 0 && cnt >= lane + 16) ? oid[warp][lane]
                                                   : oid[warp][0];
            oid[warp][lane] = v;
        }
        __syncwarp();

        // ---- gather epilogue ----
        // xyz: straight from smem (lanes 0..15, k = lane)
        if (lane < KOUT) {
            float4 p = s[oid[warp][lane]];
            size_t ox = (size_t)q * KOUT + lane;
            outx[ox]          = p.x;
            outx[ox + NK]     = p.y;
            outx[ox + 2 * NK] = p.z;
        }

        // feat: 2 passes over channel halves; coalesced row loads ->
        // XOR-swizzled stage -> channel-major 64B-segment stores.
        int ldrow = lane >> 3;           // 0..3 row-within-group
        int ldlc  = lane & 7;            // chunk within half
        int k     = lane & 15;
        int sub   = lane >> 4;
#pragma unroll
        for (int p = 0; p < 2; p++) {
#pragma unroll
            for (int i = 0; i < 4; i++) {
                int row = 4 * i + ldrow;
                int id = oid[warp][row];
                float4 v = *((const float4*)(fb + (size_t)id * 64)
                             + (p * 8 + ldlc));
                stage[warp][row * 8 + (ldlc ^ (row & 7))] = v;
            }
            __syncwarp();
#pragma unroll
            for (int t = 0; t < 4; t++) {
                int lc = sub * 4 + t;
                float4 v = stage[warp][k * 8 + (lc ^ (k & 7))];
                float* o = outf + (size_t)((p * 8 + lc) * 4) * NK
                                + (size_t)q * KOUT + k;
                o[0]      = v.x;
                o[NK]     = v.y;
                o[2 * NK] = v.z;
                o[3 * NK] = v.w;
            }
            __syncwarp();
        }
    }
}

extern "C" void kernel_launch(void* const* d_in, const int* in_sizes, int n_in,
                              void* d_out, int out_size) {
    const float* xyz  = (const float*)d_in[0];
    const float* feat = (const float*)d_in[1];
    float* out = (float*)d_out;

    cudaFuncSetAttribute(fused_kernel,
                         cudaFuncAttributeMaxDynamicSharedMemorySize,
                         NPTS * sizeof(float4));

    build_kernel<<<BATCH, 512>>>(xyz);
    fused_kernel<<<NBLOCKS, TPB, NPTS * sizeof(float4)>>>(feat, out);
}

// round 15
// speedup vs baseline: 1.2129x; 1.2129x over previous
#include <cuda_runtime.h>
#include <cstdint>

#define BATCH 4
#define NPTS 4096
#define KOUT 16
#define NEED 31                 // rank 0 plus ranks 16..30
#define R2 256.0f
#define TPB 512
#define WARPS (TPB / 32)        // 16
#define NBLOCKS 296             // 148 SMs * 2 resident blocks
#define WPB_PER_BATCH ((NBLOCKS / BATCH) * WARPS)        // 1184
#define PERIOD (NPTS + WPB_PER_BATCH)                    // 5280
#define NK ((size_t)NPTS * KOUT)                         // 65536

#define NC 12
#define NCELLS (NC * NC * NC)   // 1728
#define CELL 24.0f
#define GOFF 144.0f
#define INV_CELL (1.0f / 24.0f)
#define PRUNE_R2 289.0f         // 17^2 margin >> fp fuzz at the d2<256 edge

// steal counters: never reset; q = ctr % PERIOD is deterministic per replay
__device__ unsigned g_ctr[BATCH];

// exact arithmetic (matches reference decisions; rel_err 0.0 with this)
static __device__ __forceinline__ float dist2(float4 a, float4 b) {
    float dot = __fadd_rn(
        __fadd_rn(__fmul_rn(a.x, b.x), __fmul_rn(a.y, b.y)),
        __fmul_rn(a.z, b.z));
    return __fsub_rn(__fadd_rn(a.w, b.w), __fmul_rn(2.0f, dot));
}

static __device__ __forceinline__ int cellco(float v) {
    int c = (int)floorf((v + GOFF) * INV_CELL);
    return c < 0 ? 0 : (c > NC - 1 ? NC - 1 : c);
}

// ---------------------------------------------------------------------------
// One fused kernel. Each block: (1) redundantly builds its batch's grid CSR
// in smem (order within cells is atomic-arbitrary; outputs order-independent
// via the hit bitmap), (2) warp-per-query pruned flattened scan -> bitmap ->
// rank decode -> transposing gather epilogue.
// ---------------------------------------------------------------------------
__global__ void __launch_bounds__(TPB, 2) fused_kernel(
        const float* __restrict__ xyz,
        const float* __restrict__ feat,
        float* __restrict__ out) {
    extern __shared__ float4 s[];                        // 4096 f4 = 64KB
    // pool: build-phase hist (8KB) then per-warp bitmap/stage (2KB each)
    __shared__ __align__(16) unsigned char pool[WARPS * 2048];   // 32KB
    __shared__ unsigned short perm16[NPTS];              // 8KB
    __shared__ unsigned short starts16[NCELLS + 1];      // 3.5KB
    __shared__ unsigned short segbase[WARPS][32];        // 1KB
    __shared__ unsigned short segst[WARPS][32];          // 1KB
    __shared__ unsigned short oid[WARPS][KOUT + 1];      // 0.5KB
    __shared__ int wsums[16];

    int b = blockIdx.x % BATCH;
    const float* xb = xyz + (size_t)b * NPTS * 3;
    int t = threadIdx.x;
    int lane = t & 31, warp = t >> 5;

    // ============== build phase (redundant per block) ==============
    int* hist = (int*)pool;                              // 2048 ints
    for (int i = t; i < 2048; i += TPB) hist[i] = 0;
    __syncthreads();

    int mycell[NPTS / TPB];
#pragma unroll
    for (int j = 0; j < NPTS / TPB; j++) {
        int i = t + j * TPB;
        float x = xb[3 * i], y = xb[3 * i + 1], z = xb[3 * i + 2];
        float w = __fadd_rn(__fadd_rn(__fmul_rn(x, x), __fmul_rn(y, y)),
                            __fmul_rn(z, z));
        s[i] = make_float4(x, y, z, w);
        int cell = (cellco(x) * NC + cellco(y)) * NC + cellco(z);
        mycell[j] = cell;
        atomicAdd(&hist[cell], 1);
    }
    __syncthreads();

    // block exclusive scan over 2048 counts (4 per thread)
    int h0 = hist[4 * t + 0], h1 = hist[4 * t + 1];
    int h2 = hist[4 * t + 2], h3 = hist[4 * t + 3];
    int v = h0 + h1 + h2 + h3;
    int pre = v;
#pragma unroll
    for (int o = 1; o < 32; o <<= 1) {
        int u = __shfl_up_sync(0xffffffffu, pre, o);
        if (lane >= o) pre += u;
    }
    if (lane == 31) wsums[warp] = pre;
    __syncthreads();
    if (t == 0) {
        int acc = 0;
        for (int i = 0; i < 16; i++) { int tmp = wsums[i]; wsums[i] = acc; acc += tmp; }
    }
    __syncthreads();
    int e = pre - v + wsums[warp];
    __syncthreads();                     // all hist reads done
    hist[4 * t + 0] = e;
    hist[4 * t + 1] = e + h0;
    hist[4 * t + 2] = e + h0 + h1;
    hist[4 * t + 3] = e + h0 + h1 + h2;
    if (4 * t < NCELLS) {
        starts16[4 * t + 0] = (unsigned short)e;
        starts16[4 * t + 1] = (unsigned short)(e + h0);
        starts16[4 * t + 2] = (unsigned short)(e + h0 + h1);
        starts16[4 * t + 3] = (unsigned short)(e + h0 + h1 + h2);
    }
    if (t == 0) starts16[NCELLS] = (unsigned short)NPTS;
    __syncthreads();

#pragma unroll
    for (int j = 0; j < NPTS / TPB; j++) {
        int i = t + j * TPB;
        int pos = atomicAdd(&hist[mycell[j]], 1);
        perm16[pos] = (unsigned short)i;
    }
    __syncthreads();                     // hist dead; pool becomes warp areas

    // ============== query phase ==============
    unsigned* wd = (unsigned*)(pool + warp * 2048);      // bitmap [128]
    float4* stg  = (float4*)(pool + warp * 2048);        // stage  [128]
    const float* fb = feat + (size_t)b * NPTS * 64;
    float* outx = out + ((size_t)b * 3) * NK;
    float* outf = out + (size_t)BATCH * 3 * NK + ((size_t)b * 64) * NK;

    for (;;) {
        unsigned qr = 0;
        if (lane == 0) qr = atomicAdd(&g_ctr[b], 1u) % PERIOD;
        int q = __shfl_sync(0xffffffffu, (int)qr, 0);
        if (q >= NPTS) break;

        // zero bitmap
#pragma unroll
        for (int i = 0; i < 4; i++) wd[lane + 32 * i] = 0u;

        float4 pq = s[q];
        int c0x = cellco(pq.x - 17.0f), c1x = cellco(pq.x + 17.0f);
        int c0y = cellco(pq.y - 17.0f), c1y = cellco(pq.y + 17.0f);
        int c0z = cellco(pq.z - 17.0f), c1z = cellco(pq.z + 17.0f);

        // lane l < 27 evaluates one cell of the 3x3x3 neighborhood
        int len = 0, st = 0;
        if (lane < 27) {
            int ix = lane / 9, iy = (lane / 3) % 3, iz = lane % 3;
            int cx = c0x + ix, cy = c0y + iy, cz = c0z + iz;
            if (cx <= c1x && cy <= c1y && cz <= c1z) {
                float pen = 0.0f;
                {   float lo = (cx == 0) ? -1e30f : cx * CELL - GOFF;
                    float hi = (cx == NC - 1) ? 1e30f : cx * CELL - GOFF + CELL;
                    float d = fmaxf(fmaxf(lo - pq.x, pq.x - hi), 0.0f);
                    pen += d * d; }
                {   float lo = (cy == 0) ? -1e30f : cy * CELL - GOFF;
                    float hi = (cy == NC - 1) ? 1e30f : cy * CELL - GOFF + CELL;
                    float d = fmaxf(fmaxf(lo - pq.y, pq.y - hi), 0.0f);
                    pen += d * d; }
                {   float lo = (cz == 0) ? -1e30f : cz * CELL - GOFF;
                    float hi = (cz == NC - 1) ? 1e30f : cz * CELL - GOFF + CELL;
                    float d = fmaxf(fmaxf(lo - pq.z, pq.z - hi), 0.0f);
                    pen += d * d; }
                if (pen < PRUNE_R2) {
                    int cell = (cx * NC + cy) * NC + cz;
                    st = starts16[cell];
                    len = (int)starts16[cell + 1] - st;
                }
            }
        }
        // warp scan of segment lengths -> bases, total T
        int prel = len;
#pragma unroll
        for (int o = 1; o < 32; o <<= 1) {
            int u = __shfl_up_sync(0xffffffffu, prel, o);
            if (lane >= o) prel += u;
        }
        int T = __shfl_sync(0xffffffffu, prel, 31);
        segbase[warp][lane] = (lane < 27) ? (unsigned short)(prel - len)
                                          : (unsigned short)0xFFFF;
        segst[warp][lane] = (unsigned short)st;
        __syncwarp();

        // dense flattened candidate scan
        int cnt = 0;
        for (int j0 = 0; j0 < T; j0 += 32) {
            int pos = j0 + lane;
            bool ok = pos < T;
            // max seg with base <= pos (base[0]=0, bases non-decreasing)
            int sg = 0;
#pragma unroll
            for (int step = 16; step >= 1; step >>= 1) {
                int cand = sg + step;
                if (cand < 32 && (int)segbase[warp][cand] <= pos) sg = cand;
            }
            int j = (int)segst[warp][sg] + pos - (int)segbase[warp][sg];
            int idx = ok ? (int)perm16[j] : 0;
            float4 p = s[idx];
            bool hit = ok && (dist2(pq, p) < R2);
            unsigned m = __ballot_sync(0xffffffffu, hit);
            if (hit) atomicOr(&wd[idx >> 5], 1u << (idx & 31));
            cnt += __popc(m);
        }
        __syncwarp();

        // ---- decode: rank 0 and ranks 16..30 from the hit bitmap ----
        int base = 0;
#pragma unroll
        for (int g = 0; g < 4; g++) {
            if (base >= NEED) break;
            int wi = 32 * g + lane;
            unsigned w = wd[wi];
            int pc = __popc(w);
            int prr = pc;                          // inclusive warp scan
#pragma unroll
            for (int o = 1; o < 32; o <<= 1) {
                int u = __shfl_up_sync(0xffffffffu, prr, o);
                if (lane >= o) prr += u;
            }
            int lo = base + prr - pc;              // first rank in my word
            if (w && lo < NEED) {
                unsigned ww = w;
                int r = lo;
                while (ww && r < NEED) {
                    int bit = __ffs(ww) - 1;
                    ww &= ww - 1;
                    if (r == 0)
                        oid[warp][0] = (unsigned short)(32 * wi + bit);
                    else if (r >= 16)
                        oid[warp][r - 15] = (unsigned short)(32 * wi + bit);
                    r++;
                }
            }
            base += __shfl_sync(0xffffffffu, prr, 31);
        }
        __syncwarp();

        // finalize ids (padding with first hit)
        if (lane < KOUT) {
            unsigned short vv = (lane > 0 && cnt >= lane + 16)
                              ? oid[warp][lane] : oid[warp][0];
            oid[warp][lane] = vv;
        }
        __syncwarp();

        // ---- gather epilogue ----
        if (lane < KOUT) {
            float4 p = s[oid[warp][lane]];
            size_t ox = (size_t)q * KOUT + lane;
            outx[ox]          = p.x;
            outx[ox + NK]     = p.y;
            outx[ox + 2 * NK] = p.z;
        }

        int ldrow = lane >> 3;           // 0..3 row-within-group
        int ldlc  = lane & 7;            // chunk within half
        int k     = lane & 15;
        int sub   = lane >> 4;
#pragma unroll
        for (int p = 0; p < 2; p++) {
#pragma unroll
            for (int i = 0; i < 4; i++) {
                int row = 4 * i + ldrow;
                int id = oid[warp][row];
                float4 vv = *((const float4*)(fb + (size_t)id * 64)
                              + (p * 8 + ldlc));
                stg[row * 8 + (ldlc ^ (row & 7))] = vv;
            }
            __syncwarp();
#pragma unroll
            for (int u = 0; u < 4; u++) {
                int lc = sub * 4 + u;
                float4 vv = stg[k * 8 + (lc ^ (k & 7))];
                float* o = outf + (size_t)((p * 8 + lc) * 4) * NK
                                + (size_t)q * KOUT + k;
                o[0]      = vv.x;
                o[NK]     = vv.y;
                o[2 * NK] = vv.z;
                o[3 * NK] = vv.w;
            }
            __syncwarp();
        }
    }
}

extern "C" void kernel_launch(void* const* d_in, const int* in_sizes, int n_in,
                              void* d_out, int out_size) {
    const float* xyz  = (const float*)d_in[0];
    const float* feat = (const float*)d_in[1];
    float* out = (float*)d_out;

    cudaFuncSetAttribute(fused_kernel,
                         cudaFuncAttributeMaxDynamicSharedMemorySize,
                         NPTS * sizeof(float4));

    fused_kernel<<<NBLOCKS, TPB, NPTS * sizeof(float4)>>>(xyz, feat, out);
}

// round 16
// speedup vs baseline: 1.2954x; 1.0681x over previous
#include <cuda_runtime.h>
#include <cstdint>

#define BATCH 4
#define NPTS 4096
#define KOUT 16
#define NEED 31                 // rank 0 plus ranks 16..30
#define R2 256.0f
#define TPB 512
#define WARPS (TPB / 32)        // 16
#define NBLOCKS 296             // 148 SMs * 2 resident blocks
#define PERIOD 5280             // NPTS + 74*16 warps per batch
#define NK ((size_t)NPTS * KOUT)

#define NC 12
#define NCELLS (NC * NC * NC)   // 1728
#define CELL 24.0f
#define GOFF 144.0f
#define INV_CELL (1.0f / 24.0f)
#define PRUNE_R2 289.0f         // 17^2 margin >> fp fuzz at the d2<256 edge
#define FULL 0xffffffffu

// steal counters: never reset; q = ctr % PERIOD is deterministic per replay
__device__ unsigned g_ctr[BATCH];

// exact arithmetic (matches reference decisions; rel_err 0.0 with this)
static __device__ __forceinline__ float dist2(float4 a, float4 b) {
    float dot = __fadd_rn(
        __fadd_rn(__fmul_rn(a.x, b.x), __fmul_rn(a.y, b.y)),
        __fmul_rn(a.z, b.z));
    return __fsub_rn(__fadd_rn(a.w, b.w), __fmul_rn(2.0f, dot));
}

static __device__ __forceinline__ int cellco(float v) {
    int c = (int)floorf((v + GOFF) * INV_CELL);
    return c < 0 ? 0 : (c > NC - 1 ? NC - 1 : c);
}

// ---------------------------------------------------------------------------
// One fused kernel. Build: cell-sorted point array s (CSR), perm16 = orig ids.
// Query (warp each, work-stealing): pruned flattened scan over CONTIGUOUS
// sorted candidates -> hit bitmap in orig-index space -> rank decode ->
// transposing gather epilogue. All outputs independent of scatter order.
// ---------------------------------------------------------------------------
__global__ void __launch_bounds__(TPB, 2) fused_kernel(
        const float* __restrict__ xyz,
        const float* __restrict__ feat,
        float* __restrict__ out) {
    extern __shared__ float4 s[];                        // 4096 f4 = 64KB (sorted)
    // pool: build hist (8KB) then per-warp bitmap(512B)/stage(2KB) regions
    __shared__ __align__(16) unsigned char pool[WARPS * 2048];   // 32KB
    __shared__ unsigned short perm16[NPTS];              // 8KB: pos -> orig id
    __shared__ unsigned short starts16[NCELLS + 1];      // 3.5KB
    __shared__ unsigned short oid[WARPS][KOUT + 1];      // 0.5KB
    __shared__ int wsums[16];

    int b = blockIdx.x % BATCH;
    const float* xb = xyz + (size_t)b * NPTS * 3;
    int t = threadIdx.x;
    int lane = t & 31, warp = t >> 5;

    // ============== build phase (redundant per block) ==============
    int* hist = (int*)pool;                              // 2048 ints
    for (int i = t; i < 2048; i += TPB) hist[i] = 0;
    __syncthreads();

#pragma unroll
    for (int j = 0; j < NPTS / TPB; j++) {
        int i = t + j * TPB;
        float x = xb[3 * i], y = xb[3 * i + 1], z = xb[3 * i + 2];
        int cell = (cellco(x) * NC + cellco(y)) * NC + cellco(z);
        atomicAdd(&hist[cell], 1);
    }
    __syncthreads();

    // block exclusive scan over 2048 counts (4 per thread)
    int h0 = hist[4 * t + 0], h1 = hist[4 * t + 1];
    int h2 = hist[4 * t + 2], h3 = hist[4 * t + 3];
    int v = h0 + h1 + h2 + h3;
    int pre = v;
#pragma unroll
    for (int o = 1; o < 32; o <<= 1) {
        int u = __shfl_up_sync(FULL, pre, o);
        if (lane >= o) pre += u;
    }
    if (lane == 31) wsums[warp] = pre;
    __syncthreads();
    if (t == 0) {
        int acc = 0;
        for (int i = 0; i < 16; i++) { int tmp = wsums[i]; wsums[i] = acc; acc += tmp; }
    }
    __syncthreads();
    int e = pre - v + wsums[warp];
    __syncthreads();                     // all hist reads done
    hist[4 * t + 0] = e;
    hist[4 * t + 1] = e + h0;
    hist[4 * t + 2] = e + h0 + h1;
    hist[4 * t + 3] = e + h0 + h1 + h2;
    if (4 * t < NCELLS) {
        starts16[4 * t + 0] = (unsigned short)e;
        starts16[4 * t + 1] = (unsigned short)(e + h0);
        starts16[4 * t + 2] = (unsigned short)(e + h0 + h1);
        starts16[4 * t + 3] = (unsigned short)(e + h0 + h1 + h2);
    }
    if (t == 0) starts16[NCELLS] = (unsigned short)NPTS;
    __syncthreads();

    // scatter: s sorted by cell; perm16 maps pos -> original index
#pragma unroll
    for (int j = 0; j < NPTS / TPB; j++) {
        int i = t + j * TPB;
        float x = xb[3 * i], y = xb[3 * i + 1], z = xb[3 * i + 2];
        float w = __fadd_rn(__fadd_rn(__fmul_rn(x, x), __fmul_rn(y, y)),
                            __fmul_rn(z, z));
        int cell = (cellco(x) * NC + cellco(y)) * NC + cellco(z);
        int pos = atomicAdd(&hist[cell], 1);
        s[pos] = make_float4(x, y, z, w);
        perm16[pos] = (unsigned short)i;
    }
    __syncthreads();                     // hist dead; pool -> warp regions

    // ============== query phase ==============
    unsigned* wd = (unsigned*)(pool + warp * 2048);      // bitmap [128]
    float4* stg  = (float4*)(pool + warp * 2048);        // stage  [128]
    const float* fb = feat + (size_t)b * NPTS * 64;
    float* outx = out + ((size_t)b * 3) * NK;
    float* outf = out + (size_t)BATCH * 3 * NK + ((size_t)b * 64) * NK;

    for (;;) {
        unsigned qr = 0;
        if (lane == 0) qr = atomicAdd(&g_ctr[b], 1u) % PERIOD;
        int q = __shfl_sync(FULL, (int)qr, 0);
        if (q >= NPTS) break;

        // query coords: uniform (broadcast) global loads; norm recomputed
        // with the exact build expression -> bit-identical w
        float qx = xb[3 * q], qy = xb[3 * q + 1], qz = xb[3 * q + 2];
        float qw = __fadd_rn(__fadd_rn(__fmul_rn(qx, qx), __fmul_rn(qy, qy)),
                             __fmul_rn(qz, qz));
        float4 pq = make_float4(qx, qy, qz, qw);

        // zero bitmap
#pragma unroll
        for (int i = 0; i < 4; i++) wd[lane + 32 * i] = 0u;
        __syncwarp();

        int c0x = cellco(qx - 17.0f), c1x = cellco(qx + 17.0f);
        int c0y = cellco(qy - 17.0f), c1y = cellco(qy + 17.0f);
        int c0z = cellco(qz - 17.0f), c1z = cellco(qz + 17.0f);

        // lane l < 27 evaluates one cell of the 3x3x3 neighborhood
        int len = 0, st = 0;
        if (lane < 27) {
            int ix = lane / 9, iy = (lane / 3) % 3, iz = lane % 3;
            int cx = c0x + ix, cy = c0y + iy, cz = c0z + iz;
            if (cx <= c1x && cy <= c1y && cz <= c1z) {
                float pen = 0.0f;
                {   float lo = (cx == 0) ? -1e30f : cx * CELL - GOFF;
                    float hi = (cx == NC - 1) ? 1e30f : cx * CELL - GOFF + CELL;
                    float d = fmaxf(fmaxf(lo - qx, qx - hi), 0.0f);
                    pen += d * d; }
                {   float lo = (cy == 0) ? -1e30f : cy * CELL - GOFF;
                    float hi = (cy == NC - 1) ? 1e30f : cy * CELL - GOFF + CELL;
                    float d = fmaxf(fmaxf(lo - qy, qy - hi), 0.0f);
                    pen += d * d; }
                {   float lo = (cz == 0) ? -1e30f : cz * CELL - GOFF;
                    float hi = (cz == NC - 1) ? 1e30f : cz * CELL - GOFF + CELL;
                    float d = fmaxf(fmaxf(lo - qz, qz - hi), 0.0f);
                    pen += d * d; }
                if (pen < PRUNE_R2) {
                    int cell = (cx * NC + cy) * NC + cz;
                    st = starts16[cell];
                    len = (int)starts16[cell + 1] - st;
                }
            }
        }
        // warp inclusive scan of lengths -> per-lane base, total T
        int prel = len;
#pragma unroll
        for (int o = 1; o < 32; o <<= 1) {
            int u = __shfl_up_sync(FULL, prel, o);
            if (lane >= o) prel += u;
        }
        int T = __shfl_sync(FULL, prel, 31);
        int mybase = (lane < 27) ? (prel - len) : 65535;
        int myst = st;

        // dense flattened scan over SORTED candidates (s[j] contiguous)
        int cnt = 0;
        for (int j0 = 0; j0 < T; j0 += 32) {
            int pos = j0 + lane;
            bool ok = pos < T;
            // register binary search: max sg with base[sg] <= pos
            int sg = 0;
#pragma unroll
            for (int step = 16; step >= 1; step >>= 1) {
                int cand = sg + step;
                int bb = __shfl_sync(FULL, mybase, cand);
                if (bb <= pos) sg = cand;
            }
            int bsel = __shfl_sync(FULL, mybase, sg);
            int ssel = __shfl_sync(FULL, myst, sg);
            int j = ok ? (ssel + pos - bsel) : 0;
            float4 p = s[j];
            int idx = (int)perm16[j];
            bool hit = ok && (dist2(pq, p) < R2);
            unsigned m = __ballot_sync(FULL, hit);
            if (hit) atomicOr(&wd[idx >> 5], 1u << (idx & 31));
            cnt += __popc(m);
        }
        __syncwarp();

        // ---- decode: rank 0 and ranks 16..30 from the hit bitmap ----
        int base = 0;
#pragma unroll
        for (int g = 0; g < 4; g++) {
            if (base >= NEED) break;
            int wi = 32 * g + lane;
            unsigned w = wd[wi];
            int pc = __popc(w);
            int prr = pc;                          // inclusive warp scan
#pragma unroll
            for (int o = 1; o < 32; o <<= 1) {
                int u = __shfl_up_sync(FULL, prr, o);
                if (lane >= o) prr += u;
            }
            int lo = base + prr - pc;              // first rank in my word
            if (w && lo < NEED) {
                unsigned ww = w;
                int r = lo;
                while (ww && r < NEED) {
                    int bit = __ffs(ww) - 1;
                    ww &= ww - 1;
                    if (r == 0)
                        oid[warp][0] = (unsigned short)(32 * wi + bit);
                    else if (r >= 16)
                        oid[warp][r - 15] = (unsigned short)(32 * wi + bit);
                    r++;
                }
            }
            base += __shfl_sync(FULL, prr, 31);
        }
        __syncwarp();

        // finalize ids (padding with first hit)
        if (lane < KOUT) {
            unsigned short vv = (lane > 0 && cnt >= lane + 16)
                              ? oid[warp][lane] : oid[warp][0];
            oid[warp][lane] = vv;
        }
        __syncwarp();

        // ---- gather epilogue ----
        // xyz from global: lane = (c<<4)|kk loads coord c of oid[kk]
        {
            int kk = lane & 15, c = lane >> 4;
            int idk = oid[warp][kk];
            float v1 = xb[3 * idk + c];            // x (c=0) or y (c=1)
            size_t ox = (size_t)q * KOUT + kk;
            outx[ox + (size_t)c * NK] = v1;
            if (lane < 16) {
                float v2 = xb[3 * idk + 2];
                outx[ox + 2 * NK] = v2;
            }
        }

        // feat: 2 passes over channel halves; coalesced row loads ->
        // XOR-swizzled stage -> channel-major 64B-segment stores.
        int ldrow = lane >> 3;           // 0..3 row-within-group
        int ldlc  = lane & 7;            // chunk within half
        int k     = lane & 15;
        int sub   = lane >> 4;
#pragma unroll
        for (int pp = 0; pp < 2; pp++) {
#pragma unroll
            for (int i = 0; i < 4; i++) {
                int row = 4 * i + ldrow;
                int id = oid[warp][row];
                float4 vv = *((const float4*)(fb + (size_t)id * 64)
                              + (pp * 8 + ldlc));
                stg[row * 8 + (ldlc ^ (row & 7))] = vv;
            }
            __syncwarp();
#pragma unroll
            for (int u = 0; u < 4; u++) {
                int lc = sub * 4 + u;
                float4 vv = stg[k * 8 + (lc ^ (k & 7))];
                float* o = outf + (size_t)((pp * 8 + lc) * 4) * NK
                                + (size_t)q * KOUT + k;
                o[0]      = vv.x;
                o[NK]     = vv.y;
                o[2 * NK] = vv.z;
                o[3 * NK] = vv.w;
            }
            __syncwarp();
        }
    }
}

extern "C" void kernel_launch(void* const* d_in, const int* in_sizes, int n_in,
                              void* d_out, int out_size) {
    const float* xyz  = (const float*)d_in[0];
    const float* feat = (const float*)d_in[1];
    float* out = (float*)d_out;

    cudaFuncSetAttribute(fused_kernel,
                         cudaFuncAttributeMaxDynamicSharedMemorySize,
                         NPTS * sizeof(float4));

    fused_kernel<<<NBLOCKS, TPB, NPTS * sizeof(float4)>>>(xyz, feat, out);
}